// round 15
// baseline (speedup 1.0000x reference)
#include <cuda_runtime.h>
#include <cuda_fp16.h>

#define MAX_N 20000
#define MAX_E 640000
#define SLOT_CAP 96   // >= 11 sigma above mean degree 32; overflow ~impossible

// Scratch (device globals; no allocation allowed)
// h stored as fp16: 512 halves per node = 64 uint4 (1KB/node, 20.5MB total)
__device__ uint4 g_hu[MAX_N * 64];
__device__ int g_cnt[MAX_N];
__device__ int g_slots[MAX_N * SLOT_CAP];

__device__ __forceinline__ int clampi(int v, int hi) {
    v = v < 0 ? 0 : v;
    return v > hi ? hi : v;
}

// pack two fp32 -> half2 bits (rn, monotone)
__device__ __forceinline__ unsigned int pack_h2(float x, float y) {
    __half2 h = __float22half2_rn(make_float2(x, y));
    return *(unsigned int*)&h;
}
__device__ __forceinline__ unsigned int umax_h2(unsigned int a, unsigned int b) {
    __half2 r = __hmax2(*(__half2*)&a, *(__half2*)&b);
    return *(unsigned int*)&r;
}
__device__ __forceinline__ float2 unpack_h2(unsigned int a) {
    return __half22float2(*(__half2*)&a);
}

// ---- packed f32x2 (FFMA2) helpers: PTX-only, per-half IEEE fp32 FMA ----
__device__ __forceinline__ unsigned long long pack2(float v) {
    unsigned long long r;
    asm("mov.b64 %0, {%1, %1};" : "=l"(r) : "r"(__float_as_uint(v)));
    return r;
}
__device__ __forceinline__ unsigned long long ffma2(
    unsigned long long a, unsigned long long b, unsigned long long c) {
    unsigned long long d;
    asm("fma.rn.f32x2 %0, %1, %2, %3;" : "=l"(d) : "l"(a), "l"(b), "l"(c));
    return d;
}
// u64 f32x2 -> packed half2 bits
__device__ __forceinline__ unsigned int h2_from_x2(unsigned long long p) {
    unsigned int lo = (unsigned int)p, hi = (unsigned int)(p >> 32);
    return pack_h2(__uint_as_float(lo), __uint_as_float(hi));
}

// h[n][o*4+t] = sum_f x[n][f][t] * W[o][f] + b[o]  (fp32 math, fp16 store)
// Prologue: slot-CSR fill fused in (each thread <=9 edges, batched atomics).
// Main: 256 threads = 8 warps; each warp computes TWO nodes (16 nodes/group).
// Inner loop f32x2: 16 FFMA2 + 4 packs + 3 LDS.128 per f per warp.
// smem: wt[128*128] fp32 (64KB) + xs[16 nodes * 128 float4] (32KB) + pad.
extern __shared__ float g_sm[];
__global__ void __launch_bounds__(256) gemm_kernel(
    const float4* __restrict__ x4, const float* __restrict__ W,
    const float4* __restrict__ b4, int nNodes,
    const int* __restrict__ src, const int* __restrict__ dst, int E) {
    float* wt = g_sm;                          // wt[f*128 + o], 64KB
    float4* xs = (float4*)(g_sm + 16384);      // 16 nodes x 128 float4, 32KB
    const int tid = threadIdx.x;
    const int wrp = tid >> 5, l = tid & 31;

    // ---- fused fill prologue (independent of smem/GEMM; no barrier) ----
    {
        const int gt = blockIdx.x * 256 + tid;
        const int stride = gridDim.x * 256;
        int dv[9], sv[9], pos[9];
        bool vld[9];
#pragma unroll
        for (int k = 0; k < 9; ++k) {
            int e = gt + k * stride;
            vld[k] = (e < E);
            if (vld[k]) { dv[k] = clampi(dst[e], nNodes - 1);
                          sv[k] = clampi(src[e], nNodes - 1); }
        }
#pragma unroll
        for (int k = 0; k < 9; ++k)
            if (vld[k]) pos[k] = atomicAdd(&g_cnt[dv[k]], 1);
#pragma unroll
        for (int k = 0; k < 9; ++k)
            if (vld[k] && pos[k] < SLOT_CAP)
                g_slots[dv[k] * SLOT_CAP + pos[k]] = sv[k];
        // safety tail (empty unless E > 9*stride)
        for (int e = gt + 9 * stride; e < E; e += stride) {
            int d = clampi(dst[e], nNodes - 1);
            int p = atomicAdd(&g_cnt[d], 1);
            if (p < SLOT_CAP) g_slots[d * SLOT_CAP + p] = clampi(src[e], nNodes - 1);
        }
    }

    // Transpose W into wt. o = tid&127; halves of f-range split by tid>>7.
    {
        const int o = tid & 127;
        const int jb = (tid >> 7) << 4;        // 0 or 16
        const float4* Wr = (const float4*)(W + o * 128);
#pragma unroll 8
        for (int jj = 0; jj < 16; ++jj) {
            int j = jb + jj;
            float4 w = Wr[j];
            wt[(4 * j + 0) * 128 + o] = w.x;
            wt[(4 * j + 1) * 128 + o] = w.y;
            wt[(4 * j + 2) * 128 + o] = w.z;
            wt[(4 * j + 3) * 128 + o] = w.w;
        }
    }
    const float4 bv = b4[l];   // biases for o = 4l..4l+3
    const unsigned long long b0p = pack2(bv.x), b1p = pack2(bv.y);
    const unsigned long long b2p = pack2(bv.z), b3p = pack2(bv.w);

    int nGroups = (nNodes + 15) >> 4;
    for (int g = blockIdx.x; g < nGroups; g += gridDim.x) {
        int n0 = g << 4;
        __syncthreads();  // also orders wt writes before first read
        // Stage 16 nodes: 2048 float4, 8 iters x 256 thr
#pragma unroll
        for (int k = 0; k < 8; ++k) {
            int i = (k << 8) + tid;       // 0..2047
            int node = i >> 7, off = i & 127;
            if (n0 + node < nNodes)
                xs[i] = x4[(n0 + node) * 128 + off];
        }
        __syncthreads();
        int n = n0 + 2 * wrp;             // warp's node pair: n, n+1
        if (n < nNodes) {
            // node n accs: aK = o=4l+K, (lo=(t0,t1), hi=(t2,t3))
            unsigned long long a0lo = b0p, a0hi = b0p;
            unsigned long long a1lo = b1p, a1hi = b1p;
            unsigned long long a2lo = b2p, a2hi = b2p;
            unsigned long long a3lo = b3p, a3hi = b3p;
            // node n+1 accs
            unsigned long long c0lo = b0p, c0hi = b0p;
            unsigned long long c1lo = b1p, c1hi = b1p;
            unsigned long long c2lo = b2p, c2hi = b2p;
            unsigned long long c3lo = b3p, c3hi = b3p;
            const ulonglong2* xr0 = (const ulonglong2*)(xs + (wrp << 8));
            const ulonglong2* xr1 = xr0 + 128;
            const float4* wp = (const float4*)wt + l;   // +32 per f
            ulonglong2 x0 = xr0[0];
            ulonglong2 x1 = xr1[0];
            float4 wv = wp[0];
#pragma unroll 2
            for (int f = 0; f < 128; ++f) {
                // Prefetch next f (f=127 reads pad: harmless)
                ulonglong2 xn0 = xr0[f + 1];
                ulonglong2 xn1 = xr1[f + 1];
                float4 wn = wp[(f + 1) * 32];
                unsigned long long w0 = pack2(wv.x);
                unsigned long long w1 = pack2(wv.y);
                unsigned long long w2 = pack2(wv.z);
                unsigned long long w3 = pack2(wv.w);
                a0lo = ffma2(x0.x, w0, a0lo);
                a0hi = ffma2(x0.y, w0, a0hi);
                a1lo = ffma2(x0.x, w1, a1lo);
                a1hi = ffma2(x0.y, w1, a1hi);
                a2lo = ffma2(x0.x, w2, a2lo);
                a2hi = ffma2(x0.y, w2, a2hi);
                a3lo = ffma2(x0.x, w3, a3lo);
                a3hi = ffma2(x0.y, w3, a3hi);
                c0lo = ffma2(x1.x, w0, c0lo);
                c0hi = ffma2(x1.y, w0, c0hi);
                c1lo = ffma2(x1.x, w1, c1lo);
                c1hi = ffma2(x1.y, w1, c1hi);
                c2lo = ffma2(x1.x, w2, c2lo);
                c2hi = ffma2(x1.y, w2, c2hi);
                c3lo = ffma2(x1.x, w3, c3lo);
                c3hi = ffma2(x1.y, w3, c3hi);
                x0 = xn0;
                x1 = xn1;
                wv = wn;
            }
            // halves index n*512 + 16l -> uint4 index n*64 + 2l
            uint4* hp = g_hu + n * 64 + 2 * l;
            hp[0] = make_uint4(h2_from_x2(a0lo), h2_from_x2(a0hi),
                               h2_from_x2(a1lo), h2_from_x2(a1hi));
            hp[1] = make_uint4(h2_from_x2(a2lo), h2_from_x2(a2hi),
                               h2_from_x2(a3lo), h2_from_x2(a3hi));
            if (n + 1 < nNodes) {
                uint4* hq = g_hu + (n + 1) * 64 + 2 * l;
                hq[0] = make_uint4(h2_from_x2(c0lo), h2_from_x2(c0hi),
                                   h2_from_x2(c1lo), h2_from_x2(c1hi));
                hq[1] = make_uint4(h2_from_x2(c2lo), h2_from_x2(c2hi),
                                   h2_from_x2(c3lo), h2_from_x2(c3hi));
            }
        }
    }
}

// One warp per dst node. COALESCED: lane l reads uint4 row+l (512B txn) and
// row+32+l. Thread l owns halves [8l,8l+8) and [256+8l,256+8l+8).
// Mainloop: 4 edges/iter -> 8 independent LDG.128 in flight per thread.
__global__ void gather_kernel(float4* __restrict__ out4, int nNodes) {
    int gw = (int)((blockIdx.x * blockDim.x + threadIdx.x) >> 5);
    int l = threadIdx.x & 31;
    if (gw >= nNodes) return;
    int cnt = g_cnt[gw];
    cnt = cnt > SLOT_CAP ? SLOT_CAP : cnt;
    int s0 = gw * SLOT_CAP, s1 = s0 + cnt;
    float4* opA = out4 + gw * 128 + 2 * l;        // halves 8l..8l+7
    float4* opB = out4 + gw * 128 + 64 + 2 * l;   // halves 256+8l..+7
    if (cnt == 0) {
        float4 z = make_float4(0.f, 0.f, 0.f, 0.f);
        opA[0] = z; opA[1] = z; opB[0] = z; opB[1] = z;
        return;
    }
    const unsigned int NI2 = 0xFC00FC00u;  // half2(-inf, -inf)
    unsigned int m0 = NI2, m1 = NI2, m2 = NI2, m3 = NI2;
    unsigned int m4 = NI2, m5 = NI2, m6 = NI2, m7 = NI2;
    const uint4* hb = g_hu;
    int e = s0;
    for (; e + 4 <= s1; e += 4) {
        int sa = g_slots[e],     sb = g_slots[e + 1];
        int sc = g_slots[e + 2], sd = g_slots[e + 3];
        const uint4* pa = hb + sa * 64 + l;
        const uint4* pb = hb + sb * 64 + l;
        const uint4* pc = hb + sc * 64 + l;
        const uint4* pd = hb + sd * 64 + l;
        uint4 A0 = __ldg(pa), A1 = __ldg(pa + 32);
        uint4 B0 = __ldg(pb), B1 = __ldg(pb + 32);
        uint4 C0 = __ldg(pc), C1 = __ldg(pc + 32);
        uint4 D0 = __ldg(pd), D1 = __ldg(pd + 32);
        m0 = umax_h2(m0, umax_h2(umax_h2(A0.x, B0.x), umax_h2(C0.x, D0.x)));
        m1 = umax_h2(m1, umax_h2(umax_h2(A0.y, B0.y), umax_h2(C0.y, D0.y)));
        m2 = umax_h2(m2, umax_h2(umax_h2(A0.z, B0.z), umax_h2(C0.z, D0.z)));
        m3 = umax_h2(m3, umax_h2(umax_h2(A0.w, B0.w), umax_h2(C0.w, D0.w)));
        m4 = umax_h2(m4, umax_h2(umax_h2(A1.x, B1.x), umax_h2(C1.x, D1.x)));
        m5 = umax_h2(m5, umax_h2(umax_h2(A1.y, B1.y), umax_h2(C1.y, D1.y)));
        m6 = umax_h2(m6, umax_h2(umax_h2(A1.z, B1.z), umax_h2(C1.z, D1.z)));
        m7 = umax_h2(m7, umax_h2(umax_h2(A1.w, B1.w), umax_h2(C1.w, D1.w)));
    }
    for (; e < s1; ++e) {
        int sa = g_slots[e];
        const uint4* pa = hb + sa * 64 + l;
        uint4 A0 = __ldg(pa), A1 = __ldg(pa + 32);
        m0 = umax_h2(m0, A0.x);
        m1 = umax_h2(m1, A0.y);
        m2 = umax_h2(m2, A0.z);
        m3 = umax_h2(m3, A0.w);
        m4 = umax_h2(m4, A1.x);
        m5 = umax_h2(m5, A1.y);
        m6 = umax_h2(m6, A1.z);
        m7 = umax_h2(m7, A1.w);
    }
    float2 f0 = unpack_h2(m0), f1 = unpack_h2(m1);
    float2 f2 = unpack_h2(m2), f3 = unpack_h2(m3);
    float2 f4 = unpack_h2(m4), f5 = unpack_h2(m5);
    float2 f6 = unpack_h2(m6), f7 = unpack_h2(m7);
    opA[0] = make_float4(f0.x, f0.y, f1.x, f1.y);
    opA[1] = make_float4(f2.x, f2.y, f3.x, f3.y);
    opB[0] = make_float4(f4.x, f4.y, f5.x, f5.y);
    opB[1] = make_float4(f6.x, f6.y, f7.x, f7.y);
}

extern "C" void kernel_launch(void* const* d_in, const int* in_sizes, int n_in,
                              void* d_out, int out_size) {
    const float* x = (const float*)d_in[0];
    const int* ei = (const int*)d_in[1];      // int32 (JAX x64 disabled)
    const float* W = (const float*)d_in[2];
    const float* b = (const float*)d_in[3];
    float* out = (float*)d_out;

    int nNodes = in_sizes[0] / 512;   // F*T = 128*4
    int E = in_sizes[1] / 2;

    const int* src = ei;          // edge_index[0]
    const int* dst = ei + E;      // edge_index[1]

    // wt 64KB + xs 32KB + 64B prefetch pad
    const int GEMM_SMEM = (16384 + 8192 + 16) * 4;   // 98,368 B
    static bool attr_done = false;
    if (!attr_done) {
        cudaFuncSetAttribute(gemm_kernel,
                             cudaFuncAttributeMaxDynamicSharedMemorySize,
                             GEMM_SMEM);
        attr_done = true;
    }

    // Serial, single-stream (stream overlap empirically regressed: R6/R7).
    int* d_cnt;
    cudaGetSymbolAddress((void**)&d_cnt, g_cnt);
    cudaMemsetAsync(d_cnt, 0, nNodes * sizeof(int), 0);

    gemm_kernel<<<296, 256, GEMM_SMEM>>>((const float4*)x, W,
                                         (const float4*)b, nNodes,
                                         src, dst, E);

    gather_kernel<<<(nNodes + 7) / 8, 256>>>((float4*)out, nNodes);
}

// round 16
// speedup vs baseline: 1.0030x; 1.0030x over previous
#include <cuda_runtime.h>
#include <cuda_fp16.h>

#define MAX_N 20000
#define MAX_E 640000
#define SLOT_CAP 96   // >= 11 sigma above mean degree 32; overflow ~impossible

// Scratch (device globals; no allocation allowed)
// h stored as fp16: 512 halves per node = 64 uint4 (1KB/node, 20.5MB total)
__device__ uint4 g_hu[MAX_N * 64];
__device__ int g_cnt[MAX_N];
__device__ int g_slots[MAX_N * SLOT_CAP];

__device__ __forceinline__ int clampi(int v, int hi) {
    v = v < 0 ? 0 : v;
    return v > hi ? hi : v;
}

// pack two fp32 -> half2 bits (rn, monotone)
__device__ __forceinline__ unsigned int pack_h2(float x, float y) {
    __half2 h = __float22half2_rn(make_float2(x, y));
    return *(unsigned int*)&h;
}
__device__ __forceinline__ unsigned int umax_h2(unsigned int a, unsigned int b) {
    __half2 r = __hmax2(*(__half2*)&a, *(__half2*)&b);
    return *(unsigned int*)&r;
}
__device__ __forceinline__ float2 unpack_h2(unsigned int a) {
    return __half22float2(*(__half2*)&a);
}

// ---- packed f32x2 (FFMA2) helpers: PTX-only, per-half IEEE fp32 FMA ----
__device__ __forceinline__ unsigned long long pack2(float v) {
    unsigned long long r;
    asm("mov.b64 %0, {%1, %1};" : "=l"(r) : "r"(__float_as_uint(v)));
    return r;
}
__device__ __forceinline__ unsigned long long ffma2(
    unsigned long long a, unsigned long long b, unsigned long long c) {
    unsigned long long d;
    asm("fma.rn.f32x2 %0, %1, %2, %3;" : "=l"(d) : "l"(a), "l"(b), "l"(c));
    return d;
}
// u64 f32x2 -> packed half2 bits
__device__ __forceinline__ unsigned int h2_from_x2(unsigned long long p) {
    unsigned int lo = (unsigned int)p, hi = (unsigned int)(p >> 32);
    return pack_h2(__uint_as_float(lo), __uint_as_float(hi));
}

// h[n][o*4+t] = sum_f x[n][f][t] * W[o][f] + b[o]  (fp32 math, fp16 store)
// Prologue: slot-CSR fill fused in (each thread <=9 edges, batched atomics).
// Main: 256 threads = 8 warps; each warp computes TWO nodes (16 nodes/group).
// Inner loop f32x2: 16 FFMA2 + 4 packs + 3 LDS.128 per f per warp.
// smem: wt[128*128] fp32 (64KB) + xs[16 nodes * 128 float4] (32KB) + pad.
extern __shared__ float g_sm[];
__global__ void __launch_bounds__(256) gemm_kernel(
    const float4* __restrict__ x4, const float* __restrict__ W,
    const float4* __restrict__ b4, int nNodes,
    const int* __restrict__ src, const int* __restrict__ dst, int E) {
    float* wt = g_sm;                          // wt[f*128 + o], 64KB
    float4* xs = (float4*)(g_sm + 16384);      // 16 nodes x 128 float4, 32KB
    const int tid = threadIdx.x;
    const int wrp = tid >> 5, l = tid & 31;

    // ---- fused fill prologue (independent of smem/GEMM; no barrier) ----
    {
        const int gt = blockIdx.x * 256 + tid;
        const int stride = gridDim.x * 256;
        int dv[9], sv[9], pos[9];
        bool vld[9];
#pragma unroll
        for (int k = 0; k < 9; ++k) {
            int e = gt + k * stride;
            vld[k] = (e < E);
            if (vld[k]) { dv[k] = clampi(dst[e], nNodes - 1);
                          sv[k] = clampi(src[e], nNodes - 1); }
        }
#pragma unroll
        for (int k = 0; k < 9; ++k)
            if (vld[k]) pos[k] = atomicAdd(&g_cnt[dv[k]], 1);
#pragma unroll
        for (int k = 0; k < 9; ++k)
            if (vld[k] && pos[k] < SLOT_CAP)
                g_slots[dv[k] * SLOT_CAP + pos[k]] = sv[k];
        // safety tail (empty unless E > 9*stride)
        for (int e = gt + 9 * stride; e < E; e += stride) {
            int d = clampi(dst[e], nNodes - 1);
            int p = atomicAdd(&g_cnt[d], 1);
            if (p < SLOT_CAP) g_slots[d * SLOT_CAP + p] = clampi(src[e], nNodes - 1);
        }
    }

    // Transpose W into wt. o = tid&127; halves of f-range split by tid>>7.
    {
        const int o = tid & 127;
        const int jb = (tid >> 7) << 4;        // 0 or 16
        const float4* Wr = (const float4*)(W + o * 128);
#pragma unroll 8
        for (int jj = 0; jj < 16; ++jj) {
            int j = jb + jj;
            float4 w = Wr[j];
            wt[(4 * j + 0) * 128 + o] = w.x;
            wt[(4 * j + 1) * 128 + o] = w.y;
            wt[(4 * j + 2) * 128 + o] = w.z;
            wt[(4 * j + 3) * 128 + o] = w.w;
        }
    }
    const float4 bv = b4[l];   // biases for o = 4l..4l+3
    const unsigned long long b0p = pack2(bv.x), b1p = pack2(bv.y);
    const unsigned long long b2p = pack2(bv.z), b3p = pack2(bv.w);

    int nGroups = (nNodes + 15) >> 4;
    for (int g = blockIdx.x; g < nGroups; g += gridDim.x) {
        int n0 = g << 4;
        __syncthreads();  // also orders wt writes before first read
        // Stage 16 nodes: 2048 float4, 8 iters x 256 thr
#pragma unroll
        for (int k = 0; k < 8; ++k) {
            int i = (k << 8) + tid;       // 0..2047
            int node = i >> 7, off = i & 127;
            if (n0 + node < nNodes)
                xs[i] = x4[(n0 + node) * 128 + off];
        }
        __syncthreads();
        int n = n0 + 2 * wrp;             // warp's node pair: n, n+1
        if (n < nNodes) {
            // node n accs: aK = o=4l+K, (lo=(t0,t1), hi=(t2,t3))
            unsigned long long a0lo = b0p, a0hi = b0p;
            unsigned long long a1lo = b1p, a1hi = b1p;
            unsigned long long a2lo = b2p, a2hi = b2p;
            unsigned long long a3lo = b3p, a3hi = b3p;
            // node n+1 accs
            unsigned long long c0lo = b0p, c0hi = b0p;
            unsigned long long c1lo = b1p, c1hi = b1p;
            unsigned long long c2lo = b2p, c2hi = b2p;
            unsigned long long c3lo = b3p, c3hi = b3p;
            const ulonglong2* xr0 = (const ulonglong2*)(xs + (wrp << 8));
            const ulonglong2* xr1 = xr0 + 128;
            const float4* wp = (const float4*)wt + l;   // +32 per f
            ulonglong2 x0 = xr0[0];
            ulonglong2 x1 = xr1[0];
            float4 wv = wp[0];
#pragma unroll 2
            for (int f = 0; f < 128; ++f) {
                // Prefetch next f (f=127 reads pad: harmless)
                ulonglong2 xn0 = xr0[f + 1];
                ulonglong2 xn1 = xr1[f + 1];
                float4 wn = wp[(f + 1) * 32];
                unsigned long long w0 = pack2(wv.x);
                unsigned long long w1 = pack2(wv.y);
                unsigned long long w2 = pack2(wv.z);
                unsigned long long w3 = pack2(wv.w);
                a0lo = ffma2(x0.x, w0, a0lo);
                a0hi = ffma2(x0.y, w0, a0hi);
                a1lo = ffma2(x0.x, w1, a1lo);
                a1hi = ffma2(x0.y, w1, a1hi);
                a2lo = ffma2(x0.x, w2, a2lo);
                a2hi = ffma2(x0.y, w2, a2hi);
                a3lo = ffma2(x0.x, w3, a3lo);
                a3hi = ffma2(x0.y, w3, a3hi);
                c0lo = ffma2(x1.x, w0, c0lo);
                c0hi = ffma2(x1.y, w0, c0hi);
                c1lo = ffma2(x1.x, w1, c1lo);
                c1hi = ffma2(x1.y, w1, c1hi);
                c2lo = ffma2(x1.x, w2, c2lo);
                c2hi = ffma2(x1.y, w2, c2hi);
                c3lo = ffma2(x1.x, w3, c3lo);
                c3hi = ffma2(x1.y, w3, c3hi);
                x0 = xn0;
                x1 = xn1;
                wv = wn;
            }
            // halves index n*512 + 16l -> uint4 index n*64 + 2l
            uint4* hp = g_hu + n * 64 + 2 * l;
            hp[0] = make_uint4(h2_from_x2(a0lo), h2_from_x2(a0hi),
                               h2_from_x2(a1lo), h2_from_x2(a1hi));
            hp[1] = make_uint4(h2_from_x2(a2lo), h2_from_x2(a2hi),
                               h2_from_x2(a3lo), h2_from_x2(a3hi));
            if (n + 1 < nNodes) {
                uint4* hq = g_hu + (n + 1) * 64 + 2 * l;
                hq[0] = make_uint4(h2_from_x2(c0lo), h2_from_x2(c0hi),
                                   h2_from_x2(c1lo), h2_from_x2(c1hi));
                hq[1] = make_uint4(h2_from_x2(c2lo), h2_from_x2(c2hi),
                                   h2_from_x2(c3lo), h2_from_x2(c3hi));
            }
        }
    }
}

// TWO warps per dst node: warp handles one 512B half-row (32 uint4).
// Lane l reads uint4 half*32+l of each source row: 1 coalesced LDG.128/edge.
// 4 accumulators/thread -> low regs; 4-edge unroll -> 4 LDG.128 in flight.
// Occupancy and per-thread MLP both high (R15 lesson: need the product).
__global__ void gather_kernel(float4* __restrict__ out4, int nNodes) {
    int gw2 = (int)((blockIdx.x * blockDim.x + threadIdx.x) >> 5);
    int node = gw2 >> 1, half = gw2 & 1;
    int l = threadIdx.x & 31;
    if (node >= nNodes) return;
    int cnt = g_cnt[node];
    cnt = cnt > SLOT_CAP ? SLOT_CAP : cnt;
    int s0 = node * SLOT_CAP, s1 = s0 + cnt;
    // Thread owns halves [half*256 + 8l, +8) -> float4 out idx node*128 + half*64 + 2l
    float4* op = out4 + node * 128 + half * 64 + 2 * l;
    if (cnt == 0) {
        float4 z = make_float4(0.f, 0.f, 0.f, 0.f);
        op[0] = z; op[1] = z;
        return;
    }
    const unsigned int NI2 = 0xFC00FC00u;  // half2(-inf, -inf)
    unsigned int m0 = NI2, m1 = NI2, m2 = NI2, m3 = NI2;
    const uint4* hb = g_hu + half * 32 + l;
    int e = s0;
    for (; e + 4 <= s1; e += 4) {
        int sa = g_slots[e],     sb = g_slots[e + 1];
        int sc = g_slots[e + 2], sd = g_slots[e + 3];
        uint4 A = __ldg(hb + sa * 64);
        uint4 B = __ldg(hb + sb * 64);
        uint4 C = __ldg(hb + sc * 64);
        uint4 D = __ldg(hb + sd * 64);
        m0 = umax_h2(m0, umax_h2(umax_h2(A.x, B.x), umax_h2(C.x, D.x)));
        m1 = umax_h2(m1, umax_h2(umax_h2(A.y, B.y), umax_h2(C.y, D.y)));
        m2 = umax_h2(m2, umax_h2(umax_h2(A.z, B.z), umax_h2(C.z, D.z)));
        m3 = umax_h2(m3, umax_h2(umax_h2(A.w, B.w), umax_h2(C.w, D.w)));
    }
    for (; e < s1; ++e) {
        uint4 A = __ldg(hb + g_slots[e] * 64);
        m0 = umax_h2(m0, A.x);
        m1 = umax_h2(m1, A.y);
        m2 = umax_h2(m2, A.z);
        m3 = umax_h2(m3, A.w);
    }
    float2 f0 = unpack_h2(m0), f1 = unpack_h2(m1);
    float2 f2 = unpack_h2(m2), f3 = unpack_h2(m3);
    op[0] = make_float4(f0.x, f0.y, f1.x, f1.y);
    op[1] = make_float4(f2.x, f2.y, f3.x, f3.y);
}

extern "C" void kernel_launch(void* const* d_in, const int* in_sizes, int n_in,
                              void* d_out, int out_size) {
    const float* x = (const float*)d_in[0];
    const int* ei = (const int*)d_in[1];      // int32 (JAX x64 disabled)
    const float* W = (const float*)d_in[2];
    const float* b = (const float*)d_in[3];
    float* out = (float*)d_out;

    int nNodes = in_sizes[0] / 512;   // F*T = 128*4
    int E = in_sizes[1] / 2;

    const int* src = ei;          // edge_index[0]
    const int* dst = ei + E;      // edge_index[1]

    // wt 64KB + xs 32KB + 64B prefetch pad
    const int GEMM_SMEM = (16384 + 8192 + 16) * 4;   // 98,368 B
    static bool attr_done = false;
    if (!attr_done) {
        cudaFuncSetAttribute(gemm_kernel,
                             cudaFuncAttributeMaxDynamicSharedMemorySize,
                             GEMM_SMEM);
        attr_done = true;
    }

    // Serial, single-stream (stream overlap empirically regressed: R6/R7).
    int* d_cnt;
    cudaGetSymbolAddress((void**)&d_cnt, g_cnt);
    cudaMemsetAsync(d_cnt, 0, nNodes * sizeof(int), 0);

    gemm_kernel<<<296, 256, GEMM_SMEM>>>((const float4*)x, W,
                                         (const float4*)b, nNodes,
                                         src, dst, E);

    // 2 warps per node -> total warps = 2*nNodes; 8 warps per 256-thr block
    gather_kernel<<<(2 * nNodes + 7) / 8, 256>>>((float4*)out, nNodes);
}